// round 14
// baseline (speedup 1.0000x reference)
#include <cuda_runtime.h>
#include <cuda_bf16.h>

// WTA2D: per (B,C) row of H*W=3136 fp32, t = 313th-largest, out = (t > x) ? x : 0.
//
// PERSISTENT CTAs, minimal state: grid = 888 (6/SM), each CTA loops over ~18
// rows reusing ONE 16-key register buffer (no prefetch, no reg growth vs the
// 93.5us single-shot kernel). Removes 18 grid waves + per-CTA launch overhead.
//
// Per row (R11 selection, proven exact, rel_err 0):
//   fast path: count >=2.0, 1024-bucket shared atomic histogram over [1.0,2.0)
//   via (u>>13)&0x3FF (monotone there), block pick, gather <=64, parallel
//   rank-count. Fallback: iterated raw-byte histogram rounds + ballot
//   bisection (exact for any input).

#define NROW 3136
#define KSEL 313u
#define WLO 0x3F800000u    // 1.0f
#define WHI 0x40000000u    // 2.0f
#define GRID 888

__device__ __forceinline__ unsigned u2k(unsigned u) {
    return (u & 0x80000000u) ? ~u : (u | 0x80000000u);
}
__device__ __forceinline__ float k2f(unsigned k) {
    unsigned v = (k & 0x80000000u) ? (k ^ 0x80000000u) : ~k;
    return __uint_as_float(v);
}

__global__ void __launch_bounds__(256, 6)
wta2d_kernel(const float* __restrict__ x, float* __restrict__ out, int nrows) {
    const int tid  = threadIdx.x;
    const int lane = tid & 31;
    const int warp = tid >> 5;
    const bool has4 = (tid < 16);

    __shared__ unsigned hist[1024];
    __shared__ unsigned aboveW[8], pickW[8];
    __shared__ unsigned gbuf[64];
    __shared__ unsigned sb_b, sb_rank, sb_m;
    __shared__ float sb_t;
    __shared__ int gcount;

    // initial zero (re-zeroed at end of each row iteration)
    reinterpret_cast<uint4*>(hist)[tid] = make_uint4(0u, 0u, 0u, 0u);
    if (tid < 64) gbuf[tid] = 0u;
    if (tid == 0) { gcount = 0; sb_m = 0u; }

    for (int row = blockIdx.x; row < nrows; row += GRID) {
        const size_t base = (size_t)row * NROW;
        unsigned u[16];
        const uint4* xin = reinterpret_cast<const uint4*>(x + base);
#pragma unroll
        for (int s = 0; s < 4; ++s) {
            int p = tid + s * 256;
            if (s < 3 || has4) {
                uint4 f = xin[p];
                u[4*s+0] = f.x; u[4*s+1] = f.y; u[4*s+2] = f.z; u[4*s+3] = f.w;
            } else {
                u[4*s+0] = u[4*s+1] = u[4*s+2] = u[4*s+3] = 0u;
            }
        }
        __syncthreads();                   // zeros visible

        // ---- classify: count >=2.0, histogram [1.0, 2.0) window ----
        unsigned ab = 0;
#pragma unroll
        for (int j = 0; j < 16; ++j) {
            bool valid = (j < 12) || has4;
            unsigned v = u[j];
            if (valid) {
                if (v < 0x80000000u && v >= WHI) ++ab;
                else if (v >= WLO && v < WHI)
                    atomicAdd(&hist[(v >> 13) & 0x3FFu], 1u);
            }
        }
#pragma unroll
        for (int off = 16; off >= 1; off >>= 1)
            ab += __shfl_xor_sync(0xFFFFFFFFu, ab, off);
        if (lane == 0) aboveW[warp] = ab;
        __syncthreads();                   // hist + aboveW ready

        unsigned above = 0;
#pragma unroll
        for (int w = 0; w < 8; ++w) above += aboveW[w];

        bool fb = (above >= KSEL);         // block-uniform
        unsigned bsel = 0, rin = 0, m = 0;

        if (!fb) {
            const unsigned rk = KSEL - above;
            uint4 h = reinterpret_cast<const uint4*>(hist)[tid];
            unsigned cc[4] = { h.x, h.y, h.z, h.w };
            unsigned tot = cc[0] + cc[1] + cc[2] + cc[3];
            unsigned s = tot;
#pragma unroll
            for (int off = 1; off <= 16; off <<= 1) {
                unsigned v = __shfl_down_sync(0xFFFFFFFFu, s, off);
                if (lane + off < 32) s += v;
            }
            if (lane == 0) pickW[warp] = s;
            __syncthreads();
            unsigned run = s - tot;
#pragma unroll
            for (int w = 0; w < 8; ++w) if (w > warp) run += pickW[w];
#pragma unroll
            for (int j = 3; j >= 0; --j) {
                unsigned nr = run + cc[j];
                if (nr >= rk && run < rk) {
                    sb_b    = (unsigned)(tid * 4 + j);
                    sb_rank = rk - run;
                    sb_m    = cc[j];
                }
                run = nr;
            }
            __syncthreads();
            fb   = (sb_m == 0u);
            bsel = sb_b; rin = sb_rank; m = sb_m;
        }

        if (!fb && m <= 64u) {
#pragma unroll
            for (int j = 0; j < 16; ++j) {
                bool valid = (j < 12) || has4;
                unsigned v = u[j];
                if (valid && v >= WLO && v < WHI && ((v >> 13) & 0x3FFu) == bsel) {
                    int p = atomicAdd(&gcount, 1);
                    if (p < 64) gbuf[p] = v;   // positives: raw order == value order
                }
            }
            __syncthreads();
            if (tid < 64) {
                int n = gcount;
                if (tid < n) {
                    unsigned k = gbuf[tid];
                    unsigned g = 0, e = 0;
#pragma unroll
                    for (int q = 0; q < 16; ++q) {
                        uint4 v = reinterpret_cast<const uint4*>(gbuf)[q];
                        g += (v.x > k) + (v.y > k) + (v.z > k) + (v.w > k);
                        e += (v.x == k) + (v.y == k) + (v.z == k) + (v.w == k);
                    }
                    if (g < rin && rin <= g + e) sb_t = __uint_as_float(k);
                }
            }
        } else if (!fb) {
            fb = true;
        }

        if (fb) {
            // ---- generic fallback: iterated byte rounds (exact) ----
            hist[tid] = 0u;
            if (tid == 0) gcount = 0;
            __syncthreads();
#pragma unroll
            for (int j = 0; j < 16; ++j) {
                bool valid = (j < 12) || has4;
                if (valid) atomicAdd(&hist[u[j] >> 24], 1u);
            }
            __syncthreads();
            if (warp == 0) {
                int o0 = lane * 8;
                unsigned cc[8];
#pragma unroll
                for (int j = 0; j < 8; ++j) {
                    int o = o0 + j;
                    int u8 = (o < 128) ? (127 - o) : o;
                    cc[j] = hist[u8];
                }
                unsigned tot = cc[0]+cc[1]+cc[2]+cc[3]+cc[4]+cc[5]+cc[6]+cc[7];
                unsigned p = tot;
#pragma unroll
                for (int off = 1; off <= 16; off <<= 1) {
                    unsigned v = __shfl_up_sync(0xFFFFFFFFu, p, off);
                    if (lane >= off) p += v;
                }
                unsigned run = p - tot;
#pragma unroll
                for (int j = 0; j < 8; ++j) {
                    unsigned nr = run + cc[j];
                    if (nr >= KSEL && run < KSEL) {
                        int o = o0 + j;
                        unsigned u8 = (o < 128) ? (unsigned)(127 - o) : (unsigned)o;
                        sb_b    = u8 | ((o >= 128) ? 256u : 0u);
                        sb_rank = KSEL - run;
                        sb_m    = cc[j];
                    }
                    run = nr;
                }
            }
            __syncthreads();
            const unsigned X = (sb_b & 256u) ? 0xFFu : 0u;
            unsigned U  = sb_b & 0xFFu;
            unsigned K  = X ? (255u - U) : (U + 128u);
            unsigned rk = sb_rank;
            unsigned mm = sb_m;
            int bits = 24;
            while (mm > 64u && bits > 0) {
                hist[tid] = 0u;
                __syncthreads();
#pragma unroll
                for (int j = 0; j < 16; ++j) {
                    bool valid = (j < 12) || has4;
                    if (valid && (u[j] >> bits) == U)
                        atomicAdd(&hist[((u[j] >> (bits - 8)) & 0xFFu) ^ X], 1u);
                }
                __syncthreads();
                if (warp == 0) {
                    unsigned rcur = rk;
                    const uint4* h4 = reinterpret_cast<const uint4*>(hist) + lane * 2;
                    uint4 v0 = h4[0], v1 = h4[1];
                    unsigned cc[8] = { v0.x, v0.y, v0.z, v0.w, v1.x, v1.y, v1.z, v1.w };
                    unsigned tot = cc[0]+cc[1]+cc[2]+cc[3]+cc[4]+cc[5]+cc[6]+cc[7];
                    unsigned s = tot;
#pragma unroll
                    for (int off = 1; off <= 16; off <<= 1) {
                        unsigned v = __shfl_down_sync(0xFFFFFFFFu, s, off);
                        if (lane + off < 32) s += v;
                    }
                    unsigned run = s - tot;
#pragma unroll
                    for (int j = 7; j >= 0; --j) {
                        unsigned nr = run + cc[j];
                        if (nr >= rcur && run < rcur) {
                            sb_b    = (unsigned)(lane * 8 + j);
                            sb_rank = rcur - run;
                            sb_m    = cc[j];
                        }
                        run = nr;
                    }
                }
                __syncthreads();
                U  = (U << 8) | (sb_b ^ X);
                K  = (K << 8) | sb_b;
                rk = sb_rank;
                mm = sb_m;
                bits -= 8;
            }
            if (bits > 0) {
#pragma unroll
                for (int j = 0; j < 16; ++j) {
                    bool valid = (j < 12) || has4;
                    if (valid && (u[j] >> bits) == U) {
                        int p = atomicAdd(&gcount, 1);
                        if (p < 64) gbuf[p] = u2k(u[j]);
                    }
                }
                __syncthreads();
                if (warp == 0) {
                    int n = gcount; if (n > 64) n = 64;
                    unsigned ck0 = (lane      < n) ? gbuf[lane]      : 0u;
                    unsigned ck1 = (lane + 32 < n) ? gbuf[lane + 32] : 0u;
                    bool a0 = (lane < n), a1 = (lane + 32 < n);
                    unsigned r = rk;
                    unsigned tk = K << bits;
                    for (int b = bits - 1; b >= 0; --b) {
                        bool bit0 = ((ck0 >> b) & 1u) != 0u;
                        bool bit1 = ((ck1 >> b) & 1u) != 0u;
                        unsigned c = __popc(__ballot_sync(0xFFFFFFFFu, a0 && bit0))
                                   + __popc(__ballot_sync(0xFFFFFFFFu, a1 && bit1));
                        if (c >= r) { a0 = a0 && bit0; a1 = a1 && bit1; tk |= (1u << b); }
                        else        { r -= c; a0 = a0 && !bit0; a1 = a1 && !bit1; }
                    }
                    if (lane == 0) sb_t = k2f(tk);
                }
            } else {
                if (tid == 0) sb_t = __uint_as_float(U);
            }
        }
        __syncthreads();                   // sb_t visible
        const float t = sb_t;

        // ---- re-zero shared state for next row (before store, no extra bar) ----
        reinterpret_cast<uint4*>(hist)[tid] = make_uint4(0u, 0u, 0u, 0u);
        if (tid < 64) gbuf[tid] = 0u;
        if (tid == 0) { gcount = 0; sb_m = 0u; }

        // ---- mask + store: float compare ----
        float4* po = reinterpret_cast<float4*>(out + base);
#pragma unroll
        for (int s = 0; s < 4; ++s) {
            int p = tid + s * 256;
            if (s < 3 || has4) {
                float4 o;
                float fx = __uint_as_float(u[4*s+0]);
                float fy = __uint_as_float(u[4*s+1]);
                float fz = __uint_as_float(u[4*s+2]);
                float fw = __uint_as_float(u[4*s+3]);
                o.x = (fx < t) ? fx : 0.0f;
                o.y = (fy < t) ? fy : 0.0f;
                o.z = (fz < t) ? fz : 0.0f;
                o.w = (fw < t) ? fw : 0.0f;
                po[p] = o;
            }
        }
        // note: next iteration's __syncthreads() (after load) orders the
        // re-zero writes above against the new row's atomics.
    }
}

extern "C" void kernel_launch(void* const* d_in, const int* in_sizes, int n_in,
                              void* d_out, int out_size) {
    const float* x = (const float*)d_in[0];
    float* out = (float*)d_out;
    int rows = in_sizes[0] / NROW;   // 16384
    int grid = (rows < GRID) ? rows : GRID;
    wta2d_kernel<<<grid, 256>>>(x, out, rows);
}